// round 1
// baseline (speedup 1.0000x reference)
#include <cuda_runtime.h>

// out[b, i] = x[b, i] * diagonal[i]
// x: [8192, 4096] f32, diagonal: [4096] f32, out: [8192, 4096] f32
// Pure HBM-streaming kernel, float4 vectorized.

static constexpr int SIZE  = 4096;
static constexpr int BATCH = 8192;
static constexpr long long TOTAL_V4 = (long long)SIZE * BATCH / 4;  // 8,388,608
static constexpr int SIZE_V4 = SIZE / 4;                            // 1024

__global__ void diag_scale_kernel(const float4* __restrict__ x,
                                  const float4* __restrict__ diag,
                                  float4* __restrict__ out)
{
    long long i = (long long)blockIdx.x * blockDim.x + threadIdx.x;
    if (i >= TOTAL_V4) return;

    // Column (in float4 units) within the row; diagonal broadcast over rows.
    int c = (int)(i & (SIZE_V4 - 1));

    float4 xv = x[i];
    float4 dv = __ldg(&diag[c]);   // 16 KiB table — L1/L2 resident

    float4 ov;
    ov.x = xv.x * dv.x;
    ov.y = xv.y * dv.y;
    ov.z = xv.z * dv.z;
    ov.w = xv.w * dv.w;
    out[i] = ov;
}

extern "C" void kernel_launch(void* const* d_in, const int* in_sizes, int n_in,
                              void* d_out, int out_size)
{
    const float4* x    = (const float4*)d_in[0];
    const float4* diag = (const float4*)d_in[1];
    float4*       out  = (float4*)d_out;

    const int threads = 256;
    const int blocks  = (int)((TOTAL_V4 + threads - 1) / threads);  // 32768
    diag_scale_kernel<<<blocks, threads>>>(x, diag, out);
}

// round 2
// speedup vs baseline: 1.0118x; 1.0118x over previous
#include <cuda_runtime.h>

// out[b, i] = x[b, i] * diagonal[i]
// x: [8192, 4096] f32, diagonal: [4096] f32, out: [8192, 4096] f32
// HBM-streaming, 4x float4 per thread (MLP=4), streaming cache hints.

static constexpr int SIZE  = 4096;
static constexpr int BATCH = 8192;
static constexpr long long TOTAL_V4 = (long long)SIZE * BATCH / 4;  // 8,388,608
static constexpr int SIZE_V4 = SIZE / 4;                            // 1024
static constexpr int VPT = 4;          // float4 per thread
static constexpr int THREADS = 256;

__global__ __launch_bounds__(THREADS)
void diag_scale_kernel(const float4* __restrict__ x,
                       const float4* __restrict__ diag,
                       float4* __restrict__ out)
{
    // Each block owns a contiguous chunk of THREADS*VPT float4s.
    long long base = (long long)blockIdx.x * (THREADS * VPT) + threadIdx.x;

    // Front-batched independent loads: MLP_p1 = 4.
    float4 xv[VPT];
    float4 dv[VPT];
#pragma unroll
    for (int k = 0; k < VPT; k++) {
        long long i = base + (long long)k * THREADS;
        xv[k] = __ldcs(&x[i]);                       // read-once: evict-streaming
        dv[k] = __ldg(&diag[(int)(i & (SIZE_V4 - 1))]);  // 16 KiB, L1-resident
    }

#pragma unroll
    for (int k = 0; k < VPT; k++) {
        long long i = base + (long long)k * THREADS;
        float4 ov;
        ov.x = xv[k].x * dv[k].x;
        ov.y = xv[k].y * dv[k].y;
        ov.z = xv[k].z * dv[k].z;
        ov.w = xv[k].w * dv[k].w;
        __stcs(&out[i], ov);                         // write-once: evict-streaming
    }
}

extern "C" void kernel_launch(void* const* d_in, const int* in_sizes, int n_in,
                              void* d_out, int out_size)
{
    const float4* x    = (const float4*)d_in[0];
    const float4* diag = (const float4*)d_in[1];
    float4*       out  = (float4*)d_out;

    const int blocks = (int)(TOTAL_V4 / (THREADS * VPT));  // 8192, exact
    diag_scale_kernel<<<blocks, THREADS>>>(x, diag, out);
}